// round 15
// baseline (speedup 1.0000x reference)
#include <cuda_runtime.h>
#include <math_constants.h>

// Warp-per-row fused multi-teacher KD loss.
// R15 = R14 with deeper prefetch pipeline:
//   pre-loop L2 prefetch of iterations 1 and 2 (R14 left iter-1 unprefetched),
//   in-loop prefetch at distance 3 (was 2). Prefetch is register-free MLP —
//   the mechanism that broke the 37-38us plateau in R14 (38.5 -> 34.0).

namespace {
constexpr int NB = 8192;
constexpr int NC = 1000;
constexpr int NV4 = 250;
constexpr int NBLK = NB / 8;                       // 1024 blocks, 8 rows each
constexpr int RBLK = 32;
constexpr float L2E  = 1.4426950408889634f;        // log2(e)
constexpr float C20  = 1.4426950408889634f / 20.0f;
constexpr float C80  = 1.4426950408889634f / 80.0f; // for s4 = 4*zm
constexpr float CTHR = 1.4426950408889634f / 6.0f;
}

__device__ float g_bmin[NBLK];
__device__ float g_bmax[NBLK];
__device__ float g_bce[NBLK];
__device__ float g_bu[NBLK];
__device__ float g_bv[NBLK];
__device__ float g_partial[RBLK];

__device__ __forceinline__ float ex2(float x) {
    float r; asm("ex2.approx.ftz.f32 %0, %1;" : "=f"(r) : "f"(x)); return r;
}
__device__ __forceinline__ void pfL2(const void* p) {
    asm volatile("prefetch.global.L2 [%0];" :: "l"(p));
}

__global__ __launch_bounds__(256, 4) void row_kernel(
    const float* __restrict__ o1, const float* __restrict__ o2,
    const float* __restrict__ o3, const float* __restrict__ o4,
    const float* __restrict__ os, const int* __restrict__ tgts)
{
    __shared__ float s_min[8], s_max[8], s_ce[8], s_u[8], s_v[8];

    const int lane = threadIdx.x & 31;
    const int wid  = threadIdx.x >> 5;
    const int row  = blockIdx.x * 8 + wid;
    const size_t base = (size_t)row * NC;

    const float4* A  = reinterpret_cast<const float4*>(o1 + base) + lane;
    const float4* B  = reinterpret_cast<const float4*>(o2 + base) + lane;
    const float4* C  = reinterpret_cast<const float4*>(o3 + base) + lane;
    const float4* D4 = reinterpret_cast<const float4*>(o4 + base) + lane;
    const float4* S  = reinterpret_cast<const float4*>(os + base) + lane;

    float E[5]  = {0, 0, 0, 0, 0};
    float D[5]  = {0, 0, 0, 0, 0};
    float Es1 = 0.0f, EsT = 0.0f;
    float m1[4];
#pragma unroll
    for (int b = 0; b < 4; b++) m1[b] = -CUDART_INF_F;
    float ms4 = -CUDART_INF_F;                     // max of s4 = 4*zm

    auto body = [&](float4 va, float4 vb, float4 vc, float4 vd, float4 vs) {
        const float za[4]  = { va.x, va.y, va.z, va.w };
        const float zb[4]  = { vb.x, vb.y, vb.z, vb.w };
        const float zc[4]  = { vc.x, vc.y, vc.z, vc.w };
        const float zd[4]  = { vd.x, vd.y, vd.z, vd.w };
        const float zs4[4] = { vs.x, vs.y, vs.z, vs.w };
#pragma unroll
        for (int j = 0; j < 4; j++) {
            const float zs = zs4[j];
            Es1 += ex2(zs * L2E);
            EsT += ex2(zs * C20);
            const float s4 = (za[j] + zb[j]) + (zc[j] + zd[j]);   // 4*mimic
            const float zz[4] = { za[j], zb[j], zc[j], zd[j] };
#pragma unroll
            for (int b = 0; b < 4; b++) {
                const float z = zz[b];
                const float e = ex2(z * C20);
                E[b] += e;
                D[b]  = fmaf(e, z - zs, D[b]);
                m1[b] = fmaxf(m1[b], z);
            }
            const float em = ex2(s4 * C80);        // mimic branch via s4
            E[4] += em;
            D[4]  = fmaf(em, fmaf(s4, 0.25f, -zs), D[4]);
            ms4   = fmaxf(ms4, s4);
        }
    };

    // prime the pipeline: L2-prefetch iterations 1 and 2
    pfL2(A + 32); pfL2(B + 32); pfL2(C + 32); pfL2(D4 + 32); pfL2(S + 32);
    pfL2(A + 64); pfL2(B + 64); pfL2(C + 64); pfL2(D4 + 64); pfL2(S + 64);

#pragma unroll 1
    for (int k = 0; k < 7; k++) {
        const int o = k * 32;
        // distance-3 prefetch: lines for iteration k+3
        if (k < 4) {
            const int p = o + 96;
            pfL2(A + p); pfL2(B + p); pfL2(C + p); pfL2(D4 + p); pfL2(S + p);
        } else if (k == 4 && lane < NV4 - 224) {   // tail's lines (idx<250)
            pfL2(A + 224); pfL2(B + 224); pfL2(C + 224);
            pfL2(D4 + 224); pfL2(S + 224);
        }
        body(__ldcs(A + o), __ldcs(B + o), __ldcs(C + o),
             __ldcs(D4 + o), __ldcs(S + o));
    }
    if (lane < NV4 - 224)                          // tail: idx = 224+lane < 250
        body(__ldcs(A + 224), __ldcs(B + 224), __ldcs(C + 224),
             __ldcs(D4 + 224), __ldcs(S + 224));

    // target logits: lane 0 gathers (L2 hot), then broadcast
    const int tg = tgts[row];
    float g0 = 0, g1 = 0, g2 = 0, g3 = 0, zst = 0;
    if (lane == 0) {
        g0 = o1[base + tg]; g1 = o2[base + tg];
        g2 = o3[base + tg]; g3 = o4[base + tg];
        zst = os[base + tg];
    }

    // warp reduction: 12 sums + 5 maxes
#pragma unroll
    for (int off = 16; off; off >>= 1) {
#pragma unroll
        for (int b = 0; b < 5; b++) {
            E[b] += __shfl_xor_sync(0xffffffffu, E[b], off);
            D[b] += __shfl_xor_sync(0xffffffffu, D[b], off);
        }
#pragma unroll
        for (int b = 0; b < 4; b++)
            m1[b] = fmaxf(m1[b], __shfl_xor_sync(0xffffffffu, m1[b], off));
        ms4 = fmaxf(ms4, __shfl_xor_sync(0xffffffffu, ms4, off));
        Es1 += __shfl_xor_sync(0xffffffffu, Es1, off);
        EsT += __shfl_xor_sync(0xffffffffu, EsT, off);
    }
    const float m1m[5] = { m1[0], m1[1], m1[2], m1[3], ms4 * 0.25f };

    g0  = __shfl_sync(0xffffffffu, g0, 0);
    g1  = __shfl_sync(0xffffffffu, g1, 0);
    g2  = __shfl_sync(0xffffffffu, g2, 0);
    g3  = __shfl_sync(0xffffffffu, g3, 0);
    zst = __shfl_sync(0xffffffffu, zst, 0);
    const float g4 = ((g0 + g1) + (g2 + g3)) * 0.25f;
    const float g[5] = { g0, g1, g2, g3, g4 };

    // rare re-pass: only when some branch's max equals its target logit
    float m2[5] = { -CUDART_INF_F, -CUDART_INF_F, -CUDART_INF_F,
                    -CUDART_INF_F, -CUDART_INF_F };
    bool need = false;
#pragma unroll
    for (int b = 0; b < 5; b++) need |= (m1m[b] == g[b]);
    if (need) {                                   // warp-uniform, rare
        float n1[5], n2[5];
#pragma unroll
        for (int b = 0; b < 5; b++) { n1[b] = -CUDART_INF_F; n2[b] = -CUDART_INF_F; }
        auto top2 = [&](float4 va, float4 vb, float4 vc, float4 vd) {
            const float za[4] = { va.x, va.y, va.z, va.w };
            const float zb[4] = { vb.x, vb.y, vb.z, vb.w };
            const float zc[4] = { vc.x, vc.y, vc.z, vc.w };
            const float zd[4] = { vd.x, vd.y, vd.z, vd.w };
#pragma unroll
            for (int j = 0; j < 4; j++) {
                const float s4 = (za[j] + zb[j]) + (zc[j] + zd[j]);
                const float zz[5] = { za[j], zb[j], zc[j], zd[j], s4 * 0.25f };
#pragma unroll
                for (int b = 0; b < 5; b++) {
                    const float z = zz[b];
                    n2[b] = fmaxf(n2[b], fminf(n1[b], z));
                    n1[b] = fmaxf(n1[b], z);
                }
            }
        };
#pragma unroll 1
        for (int k = 0; k < 7; k++) {
            const int o = k * 32;
            top2(A[o], B[o], C[o], D4[o]);
        }
        if (lane < NV4 - 224)
            top2(A[224], B[224], C[224], D4[224]);
#pragma unroll
        for (int off = 16; off; off >>= 1) {
#pragma unroll
            for (int b = 0; b < 5; b++) {
                float a1 = __shfl_xor_sync(0xffffffffu, n1[b], off);
                float a2 = __shfl_xor_sync(0xffffffffu, n2[b], off);
                n2[b] = fmaxf(n2[b], fminf(n1[b], a1));
                n2[b] = fmaxf(n2[b], a2);
                n1[b] = fmaxf(n1[b], a1);
            }
        }
#pragma unroll
        for (int b = 0; b < 5; b++) m2[b] = n2[b];
    }

    if (lane == 0) {
        float te[5], ts = 0.0f;
#pragma unroll
        for (int b = 0; b < 5; b++) {
            const float mg = (m1m[b] == g[b]) ? (m1m[b] - m2[b]) : 0.0f;
            te[b] = ex2(mg * CTHR);
            ts += te[b];
        }
        const float invts = 1.0f / ts;

        const float CE   = __logf(Es1) - zst;
        const float lseT = __logf(EsT);

        // loss_row = CE*T0 + inv*(U + shift*V); U,V,T0 shift-independent
        float T0 = 0.0f, U = 0.0f, V = 0.0f;
#pragma unroll
        for (int b = 0; b < 5; b++) {
            const float thr = te[b] * invts;
            const float iE  = 1.0f / E[b];
            const float KD  = 20.0f * D[b] * iE + 400.0f * (lseT - __logf(E[b]));
            const float dK  = KD - CE;
            T0 += thr;
            U   = fmaf(thr * g[b], dK, U);
            V   = fmaf(thr, dK, V);
        }
        s_ce[wid]  = CE * T0;
        s_u[wid]   = U;
        s_v[wid]   = V;
        s_min[wid] = fminf(fminf(g[0], g[1]), fminf(g[2], g[3]));
        s_max[wid] = fmaxf(fmaxf(m1m[0], m1m[1]), fmaxf(m1m[2], m1m[3]));
    }
    __syncthreads();
    if (threadIdx.x == 0) {
        float mn = s_min[0], mx = s_max[0];
        float ce = s_ce[0], u = s_u[0], v = s_v[0];
#pragma unroll
        for (int w = 1; w < 8; w++) {
            mn = fminf(mn, s_min[w]); mx = fmaxf(mx, s_max[w]);
            ce += s_ce[w]; u += s_u[w]; v += s_v[w];
        }
        g_bmin[blockIdx.x] = mn;
        g_bmax[blockIdx.x] = mx;
        g_bce[blockIdx.x]  = ce;
        g_bu[blockIdx.x]   = u;
        g_bv[blockIdx.x]   = v;
    }
}

// 32 blocks x 32 threads: each block scans full min/max arrays (L2-hot,
// redundant, deterministic), then reduces its own 32-record slice of sums.
__global__ __launch_bounds__(32) void reduce_kernel() {
    const int t = threadIdx.x;
    const int b = blockIdx.x;

    float mn = CUDART_INF_F, mx = -CUDART_INF_F;
#pragma unroll
    for (int i = 0; i < NBLK / 32; i++) {          // 32 records each, coalesced
        const int idx = i * 32 + t;
        mn = fminf(mn, g_bmin[idx]);
        mx = fmaxf(mx, g_bmax[idx]);
    }
#pragma unroll
    for (int off = 16; off; off >>= 1) {
        mn = fminf(mn, __shfl_xor_sync(0xffffffffu, mn, off));
        mx = fmaxf(mx, __shfl_xor_sync(0xffffffffu, mx, off));
    }
    const float shift = (mn < 0.0f) ? (-mn + 1e-5f) : 0.0f;
    const float inv   = 1.0f / (mx + shift);

    const int idx = b * 32 + t;                    // own slice, one record each
    float ce = g_bce[idx];
    float u  = g_bu[idx];
    float v  = g_bv[idx];
#pragma unroll
    for (int off = 16; off; off >>= 1) {
        ce += __shfl_xor_sync(0xffffffffu, ce, off);
        u  += __shfl_xor_sync(0xffffffffu, u,  off);
        v  += __shfl_xor_sync(0xffffffffu, v,  off);
    }
    if (t == 0)
        g_partial[b] = ce + inv * fmaf(shift, v, u);
}

__global__ void final_k(float* __restrict__ out) {
    float s = g_partial[threadIdx.x];              // 32 partials, exact
#pragma unroll
    for (int off = 16; off; off >>= 1)
        s += __shfl_xor_sync(0xffffffffu, s, off);
    if (threadIdx.x == 0) out[0] = s * (1.0f / (float)NB);
}

extern "C" void kernel_launch(void* const* d_in, const int* in_sizes, int n_in,
                              void* d_out, int out_size) {
    const float* o1 = (const float*)d_in[0];
    const float* o2 = (const float*)d_in[1];
    const float* o3 = (const float*)d_in[2];
    const float* o4 = (const float*)d_in[3];
    const float* os = (const float*)d_in[4];
    const int*   tg = (const int*)d_in[5];
    (void)in_sizes; (void)n_in; (void)out_size;

    row_kernel<<<NBLK, 256>>>(o1, o2, o3, o4, os, tg);
    reduce_kernel<<<RBLK, 32>>>();
    final_k<<<1, 32>>>((float*)d_out);
}

// round 16
// speedup vs baseline: 1.0616x; 1.0616x over previous
#include <cuda_runtime.h>
#include <math_constants.h>

// Warp-per-row fused multi-teacher KD loss.
// R16 = R14 exactly (distance-2 L2 prefetch, 34.0us measured) + ONE change:
// pre-loop prefetch of iteration 1 (the only iteration R14 never prefetched).
// R15's distance-3 + 10-hint preamble regressed to 35.3 -> reverted.

namespace {
constexpr int NB = 8192;
constexpr int NC = 1000;
constexpr int NV4 = 250;
constexpr int NBLK = NB / 8;                       // 1024 blocks, 8 rows each
constexpr int RBLK = 32;
constexpr float L2E  = 1.4426950408889634f;        // log2(e)
constexpr float C20  = 1.4426950408889634f / 20.0f;
constexpr float C80  = 1.4426950408889634f / 80.0f; // for s4 = 4*zm
constexpr float CTHR = 1.4426950408889634f / 6.0f;
}

__device__ float g_bmin[NBLK];
__device__ float g_bmax[NBLK];
__device__ float g_bce[NBLK];
__device__ float g_bu[NBLK];
__device__ float g_bv[NBLK];
__device__ float g_partial[RBLK];

__device__ __forceinline__ float ex2(float x) {
    float r; asm("ex2.approx.ftz.f32 %0, %1;" : "=f"(r) : "f"(x)); return r;
}
__device__ __forceinline__ void pfL2(const void* p) {
    asm volatile("prefetch.global.L2 [%0];" :: "l"(p));
}

__global__ __launch_bounds__(256, 4) void row_kernel(
    const float* __restrict__ o1, const float* __restrict__ o2,
    const float* __restrict__ o3, const float* __restrict__ o4,
    const float* __restrict__ os, const int* __restrict__ tgts)
{
    __shared__ float s_min[8], s_max[8], s_ce[8], s_u[8], s_v[8];

    const int lane = threadIdx.x & 31;
    const int wid  = threadIdx.x >> 5;
    const int row  = blockIdx.x * 8 + wid;
    const size_t base = (size_t)row * NC;

    const float4* A  = reinterpret_cast<const float4*>(o1 + base) + lane;
    const float4* B  = reinterpret_cast<const float4*>(o2 + base) + lane;
    const float4* C  = reinterpret_cast<const float4*>(o3 + base) + lane;
    const float4* D4 = reinterpret_cast<const float4*>(o4 + base) + lane;
    const float4* S  = reinterpret_cast<const float4*>(os + base) + lane;

    float E[5]  = {0, 0, 0, 0, 0};
    float D[5]  = {0, 0, 0, 0, 0};
    float Es1 = 0.0f, EsT = 0.0f;
    float m1[4];
#pragma unroll
    for (int b = 0; b < 4; b++) m1[b] = -CUDART_INF_F;
    float ms4 = -CUDART_INF_F;                     // max of s4 = 4*zm

    auto body = [&](float4 va, float4 vb, float4 vc, float4 vd, float4 vs) {
        const float za[4]  = { va.x, va.y, va.z, va.w };
        const float zb[4]  = { vb.x, vb.y, vb.z, vb.w };
        const float zc[4]  = { vc.x, vc.y, vc.z, vc.w };
        const float zd[4]  = { vd.x, vd.y, vd.z, vd.w };
        const float zs4[4] = { vs.x, vs.y, vs.z, vs.w };
#pragma unroll
        for (int j = 0; j < 4; j++) {
            const float zs = zs4[j];
            Es1 += ex2(zs * L2E);
            EsT += ex2(zs * C20);
            const float s4 = (za[j] + zb[j]) + (zc[j] + zd[j]);   // 4*mimic
            const float zz[4] = { za[j], zb[j], zc[j], zd[j] };
#pragma unroll
            for (int b = 0; b < 4; b++) {
                const float z = zz[b];
                const float e = ex2(z * C20);
                E[b] += e;
                D[b]  = fmaf(e, z - zs, D[b]);
                m1[b] = fmaxf(m1[b], z);
            }
            const float em = ex2(s4 * C80);        // mimic branch via s4
            E[4] += em;
            D[4]  = fmaf(em, fmaf(s4, 0.25f, -zs), D[4]);
            ms4   = fmaxf(ms4, s4);
        }
    };

    // cover iteration 1 (the only one the in-loop distance-2 scheme misses)
    pfL2(A + 32); pfL2(B + 32); pfL2(C + 32); pfL2(D4 + 32); pfL2(S + 32);

#pragma unroll 1
    for (int k = 0; k < 7; k++) {
        const int o = k * 32;
        // distance-2 prefetch (register-free MLP): lines for iteration k+2
        if (k < 5) {
            const int p = o + 64;
            pfL2(A + p); pfL2(B + p); pfL2(C + p); pfL2(D4 + p); pfL2(S + p);
        } else if (k == 5 && lane < NV4 - 224) {   // tail's lines (idx<250)
            pfL2(A + 224); pfL2(B + 224); pfL2(C + 224);
            pfL2(D4 + 224); pfL2(S + 224);
        }
        body(__ldcs(A + o), __ldcs(B + o), __ldcs(C + o),
             __ldcs(D4 + o), __ldcs(S + o));
    }
    if (lane < NV4 - 224)                          // tail: idx = 224+lane < 250
        body(__ldcs(A + 224), __ldcs(B + 224), __ldcs(C + 224),
             __ldcs(D4 + 224), __ldcs(S + 224));

    // target logits: lane 0 gathers (L2 hot), then broadcast
    const int tg = tgts[row];
    float g0 = 0, g1 = 0, g2 = 0, g3 = 0, zst = 0;
    if (lane == 0) {
        g0 = o1[base + tg]; g1 = o2[base + tg];
        g2 = o3[base + tg]; g3 = o4[base + tg];
        zst = os[base + tg];
    }

    // warp reduction: 12 sums + 5 maxes
#pragma unroll
    for (int off = 16; off; off >>= 1) {
#pragma unroll
        for (int b = 0; b < 5; b++) {
            E[b] += __shfl_xor_sync(0xffffffffu, E[b], off);
            D[b] += __shfl_xor_sync(0xffffffffu, D[b], off);
        }
#pragma unroll
        for (int b = 0; b < 4; b++)
            m1[b] = fmaxf(m1[b], __shfl_xor_sync(0xffffffffu, m1[b], off));
        ms4 = fmaxf(ms4, __shfl_xor_sync(0xffffffffu, ms4, off));
        Es1 += __shfl_xor_sync(0xffffffffu, Es1, off);
        EsT += __shfl_xor_sync(0xffffffffu, EsT, off);
    }
    const float m1m[5] = { m1[0], m1[1], m1[2], m1[3], ms4 * 0.25f };

    g0  = __shfl_sync(0xffffffffu, g0, 0);
    g1  = __shfl_sync(0xffffffffu, g1, 0);
    g2  = __shfl_sync(0xffffffffu, g2, 0);
    g3  = __shfl_sync(0xffffffffu, g3, 0);
    zst = __shfl_sync(0xffffffffu, zst, 0);
    const float g4 = ((g0 + g1) + (g2 + g3)) * 0.25f;
    const float g[5] = { g0, g1, g2, g3, g4 };

    // rare re-pass: only when some branch's max equals its target logit
    float m2[5] = { -CUDART_INF_F, -CUDART_INF_F, -CUDART_INF_F,
                    -CUDART_INF_F, -CUDART_INF_F };
    bool need = false;
#pragma unroll
    for (int b = 0; b < 5; b++) need |= (m1m[b] == g[b]);
    if (need) {                                   // warp-uniform, rare
        float n1[5], n2[5];
#pragma unroll
        for (int b = 0; b < 5; b++) { n1[b] = -CUDART_INF_F; n2[b] = -CUDART_INF_F; }
        auto top2 = [&](float4 va, float4 vb, float4 vc, float4 vd) {
            const float za[4] = { va.x, va.y, va.z, va.w };
            const float zb[4] = { vb.x, vb.y, vb.z, vb.w };
            const float zc[4] = { vc.x, vc.y, vc.z, vc.w };
            const float zd[4] = { vd.x, vd.y, vd.z, vd.w };
#pragma unroll
            for (int j = 0; j < 4; j++) {
                const float s4 = (za[j] + zb[j]) + (zc[j] + zd[j]);
                const float zz[5] = { za[j], zb[j], zc[j], zd[j], s4 * 0.25f };
#pragma unroll
                for (int b = 0; b < 5; b++) {
                    const float z = zz[b];
                    n2[b] = fmaxf(n2[b], fminf(n1[b], z));
                    n1[b] = fmaxf(n1[b], z);
                }
            }
        };
#pragma unroll 1
        for (int k = 0; k < 7; k++) {
            const int o = k * 32;
            top2(A[o], B[o], C[o], D4[o]);
        }
        if (lane < NV4 - 224)
            top2(A[224], B[224], C[224], D4[224]);
#pragma unroll
        for (int off = 16; off; off >>= 1) {
#pragma unroll
            for (int b = 0; b < 5; b++) {
                float a1 = __shfl_xor_sync(0xffffffffu, n1[b], off);
                float a2 = __shfl_xor_sync(0xffffffffu, n2[b], off);
                n2[b] = fmaxf(n2[b], fminf(n1[b], a1));
                n2[b] = fmaxf(n2[b], a2);
                n1[b] = fmaxf(n1[b], a1);
            }
        }
#pragma unroll
        for (int b = 0; b < 5; b++) m2[b] = n2[b];
    }

    if (lane == 0) {
        float te[5], ts = 0.0f;
#pragma unroll
        for (int b = 0; b < 5; b++) {
            const float mg = (m1m[b] == g[b]) ? (m1m[b] - m2[b]) : 0.0f;
            te[b] = ex2(mg * CTHR);
            ts += te[b];
        }
        const float invts = 1.0f / ts;

        const float CE   = __logf(Es1) - zst;
        const float lseT = __logf(EsT);

        // loss_row = CE*T0 + inv*(U + shift*V); U,V,T0 shift-independent
        float T0 = 0.0f, U = 0.0f, V = 0.0f;
#pragma unroll
        for (int b = 0; b < 5; b++) {
            const float thr = te[b] * invts;
            const float iE  = 1.0f / E[b];
            const float KD  = 20.0f * D[b] * iE + 400.0f * (lseT - __logf(E[b]));
            const float dK  = KD - CE;
            T0 += thr;
            U   = fmaf(thr * g[b], dK, U);
            V   = fmaf(thr, dK, V);
        }
        s_ce[wid]  = CE * T0;
        s_u[wid]   = U;
        s_v[wid]   = V;
        s_min[wid] = fminf(fminf(g[0], g[1]), fminf(g[2], g[3]));
        s_max[wid] = fmaxf(fmaxf(m1m[0], m1m[1]), fmaxf(m1m[2], m1m[3]));
    }
    __syncthreads();
    if (threadIdx.x == 0) {
        float mn = s_min[0], mx = s_max[0];
        float ce = s_ce[0], u = s_u[0], v = s_v[0];
#pragma unroll
        for (int w = 1; w < 8; w++) {
            mn = fminf(mn, s_min[w]); mx = fmaxf(mx, s_max[w]);
            ce += s_ce[w]; u += s_u[w]; v += s_v[w];
        }
        g_bmin[blockIdx.x] = mn;
        g_bmax[blockIdx.x] = mx;
        g_bce[blockIdx.x]  = ce;
        g_bu[blockIdx.x]   = u;
        g_bv[blockIdx.x]   = v;
    }
}

// 32 blocks x 32 threads: each block scans full min/max arrays (L2-hot,
// redundant, deterministic), then reduces its own 32-record slice of sums.
__global__ __launch_bounds__(32) void reduce_kernel() {
    const int t = threadIdx.x;
    const int b = blockIdx.x;

    float mn = CUDART_INF_F, mx = -CUDART_INF_F;
#pragma unroll
    for (int i = 0; i < NBLK / 32; i++) {          // 32 records each, coalesced
        const int idx = i * 32 + t;
        mn = fminf(mn, g_bmin[idx]);
        mx = fmaxf(mx, g_bmax[idx]);
    }
#pragma unroll
    for (int off = 16; off; off >>= 1) {
        mn = fminf(mn, __shfl_xor_sync(0xffffffffu, mn, off));
        mx = fmaxf(mx, __shfl_xor_sync(0xffffffffu, mx, off));
    }
    const float shift = (mn < 0.0f) ? (-mn + 1e-5f) : 0.0f;
    const float inv   = 1.0f / (mx + shift);

    const int idx = b * 32 + t;                    // own slice, one record each
    float ce = g_bce[idx];
    float u  = g_bu[idx];
    float v  = g_bv[idx];
#pragma unroll
    for (int off = 16; off; off >>= 1) {
        ce += __shfl_xor_sync(0xffffffffu, ce, off);
        u  += __shfl_xor_sync(0xffffffffu, u,  off);
        v  += __shfl_xor_sync(0xffffffffu, v,  off);
    }
    if (t == 0)
        g_partial[b] = ce + inv * fmaf(shift, v, u);
}

__global__ void final_k(float* __restrict__ out) {
    float s = g_partial[threadIdx.x];              // 32 partials, exact
#pragma unroll
    for (int off = 16; off; off >>= 1)
        s += __shfl_xor_sync(0xffffffffu, s, off);
    if (threadIdx.x == 0) out[0] = s * (1.0f / (float)NB);
}

extern "C" void kernel_launch(void* const* d_in, const int* in_sizes, int n_in,
                              void* d_out, int out_size) {
    const float* o1 = (const float*)d_in[0];
    const float* o2 = (const float*)d_in[1];
    const float* o3 = (const float*)d_in[2];
    const float* o4 = (const float*)d_in[3];
    const float* os = (const float*)d_in[4];
    const int*   tg = (const int*)d_in[5];
    (void)in_sizes; (void)n_in; (void)out_size;

    row_kernel<<<NBLK, 256>>>(o1, o2, o3, o4, os, tg);
    reduce_kernel<<<RBLK, 32>>>();
    final_k<<<1, 32>>>((float*)d_out);
}